// round 11
// baseline (speedup 1.0000x reference)
#include <cuda_runtime.h>
#include <cuda_bf16.h>
#include <cstdint>

#define N_NODES 50000
#define N_EDGES 800000
#define DIM     128

#define TILE_M   64
#define N_TILES  ((N_NODES + TILE_M - 1) / TILE_M)   // 782

// ---------------- SMEM layout (bytes, dynamic) ----------------------------
#define OFF_XHI   0
#define OFF_XLO   16384
#define OFF_WHI   32768
#define OFF_WLO   65536
#define OFF_CONST 98304                  // bias/scale/offset: 3 x 512B
#define GEMM_SMEM (98304 + 1536)
#define STAGE_STRIDE 132                 // fp32 stage [64][132] overlays X tiles

// ---------------- scan partition ------------------------------------------
#define SCAN_BS   256
#define NB_SCAN   ((N_NODES + SCAN_BS - 1) / SCAN_BS)   // 196

// ---------------- scratch (__device__ globals; no allocs allowed) ---------
__device__ int   g_cnt[N_NODES];
__device__ int   g_ofs[N_NODES + 1];
__device__ int   g_cur[N_NODES];
__device__ int   g_scol[N_EDGES];
__device__ float g_sval[N_EDGES];
__device__ int   g_bsum[NB_SCAN];
__device__ int   g_bbase[NB_SCAN];

// ---------------------------------------------------------------------------
__global__ void zero_cnt_kernel(int* __restrict__ cnt) {
    int i = blockIdx.x * blockDim.x + threadIdx.x;
    if (i < N_NODES) cnt[i] = 0;
}

__global__ void count_kernel(const int* __restrict__ erow, int* __restrict__ cnt) {
    int e = blockIdx.x * blockDim.x + threadIdx.x;
    if (e < N_EDGES) atomicAdd(&cnt[erow[e]], 1);
}

__global__ void __launch_bounds__(SCAN_BS) bsum_kernel(const int* __restrict__ cnt,
                                                       int* __restrict__ bsum) {
    __shared__ int red[SCAN_BS / 32];
    int i = blockIdx.x * SCAN_BS + threadIdx.x;
    int v = (i < N_NODES) ? cnt[i] : 0;
#pragma unroll
    for (int o = 16; o; o >>= 1) v += __shfl_xor_sync(0xffffffffu, v, o);
    if ((threadIdx.x & 31) == 0) red[threadIdx.x >> 5] = v;
    __syncthreads();
    if (threadIdx.x == 0) {
        int s = 0;
#pragma unroll
        for (int w = 0; w < SCAN_BS / 32; w++) s += red[w];
        bsum[blockIdx.x] = s;
    }
}

__global__ void __launch_bounds__(256) scan_bsums(const int* __restrict__ bsum,
                                                  int* __restrict__ bbase) {
    __shared__ int sh[256];
    int t = threadIdx.x;
    sh[t] = (t < NB_SCAN) ? bsum[t] : 0;
    __syncthreads();
#pragma unroll
    for (int o = 1; o < 256; o <<= 1) {
        int v = (t >= o) ? sh[t - o] : 0;
        __syncthreads();
        sh[t] += v;
        __syncthreads();
    }
    if (t < NB_SCAN) bbase[t] = (t == 0) ? 0 : sh[t - 1];
}

__global__ void __launch_bounds__(SCAN_BS) offsets_kernel(
    const int* __restrict__ cnt, const int* __restrict__ bbase,
    int* __restrict__ ofs, int* __restrict__ cur)
{
    __shared__ int sh[SCAN_BS];
    int t = threadIdx.x;
    int i = blockIdx.x * SCAN_BS + t;
    int v = (i < N_NODES) ? cnt[i] : 0;
    sh[t] = v;
    __syncthreads();
#pragma unroll
    for (int o = 1; o < SCAN_BS; o <<= 1) {
        int u = (t >= o) ? sh[t - o] : 0;
        __syncthreads();
        sh[t] += u;
        __syncthreads();
    }
    if (i < N_NODES) {
        int excl = bbase[blockIdx.x] + sh[t] - v;
        ofs[i] = excl;
        cur[i] = excl;
    }
    if (i == N_NODES - 1) ofs[N_NODES] = N_EDGES;
}

__global__ void fill_kernel(const int* __restrict__ erow, const int* __restrict__ ecol,
                            const float* __restrict__ eval_,
                            int* __restrict__ cur,
                            int* __restrict__ scol, float* __restrict__ sval) {
    int e = blockIdx.x * blockDim.x + threadIdx.x;
    if (e >= N_EDGES) return;
    int p = atomicAdd(&cur[erow[e]], 1);
    scol[p] = ecol[e];
    sval[p] = eval_[e];
}

// ---------------------------------------------------------------------------
__device__ __forceinline__ uint32_t smem_u32(const void* p) {
    uint32_t a;
    asm("{ .reg .u64 t; cvta.to.shared.u64 t, %1; cvt.u32.u64 %0, t; }" : "=r"(a) : "l"(p));
    return a;
}
__device__ __forceinline__ void ldsm_x4(uint32_t& r0, uint32_t& r1,
                                        uint32_t& r2, uint32_t& r3, uint32_t a) {
    asm volatile("ldmatrix.sync.aligned.m8n8.x4.shared.b16 {%0,%1,%2,%3}, [%4];"
                 : "=r"(r0), "=r"(r1), "=r"(r2), "=r"(r3) : "r"(a));
}
__device__ __forceinline__ void mma_bf16(float* c, const uint32_t* a,
                                         uint32_t b0, uint32_t b1) {
    asm volatile("mma.sync.aligned.m16n8k16.row.col.f32.bf16.bf16.f32 "
                 "{%0,%1,%2,%3}, {%4,%5,%6,%7}, {%8,%9}, {%0,%1,%2,%3};"
                 : "+f"(c[0]), "+f"(c[1]), "+f"(c[2]), "+f"(c[3])
                 : "r"(a[0]), "r"(a[1]), "r"(a[2]), "r"(a[3]), "r"(b0), "r"(b1));
}
__device__ __forceinline__ uint32_t bt_off(int r, int k0) {
    return (uint32_t)(r * 256 + ((((k0 >> 3) ^ (r & 7)) & 15) << 4));
}
__device__ __forceinline__ uint32_t a_addr(uint32_t base, int m0, int kb, int lane) {
    int row = m0 + (lane & 15);
    int chunk = (kb >> 3) + (lane >> 4);
    return base + row * 256 + (((chunk ^ (row & 7)) & 15) << 4);
}
__device__ __forceinline__ uint32_t b_addr(uint32_t base, int n0, int kb, int lane) {
    int row = n0 + (lane & 7) + ((lane >> 4) << 3);
    int chunk = (kb >> 3) + ((lane >> 3) & 1);
    return base + row * 256 + (((chunk ^ (row & 7)) & 15) << 4);
}
__device__ __forceinline__ void split_store8(const float* src, char* hi_base, char* lo_base,
                                             int r, int k0) {
    float4 a = ((const float4*)src)[0];
    float4 b = ((const float4*)src)[1];
    float v[8] = {a.x, a.y, a.z, a.w, b.x, b.y, b.z, b.w};
    uint32_t hp[4], lp[4];
#pragma unroll
    for (int e = 0; e < 4; e++) {
        __nv_bfloat16 h0 = __float2bfloat16(v[2 * e]);
        __nv_bfloat16 h1 = __float2bfloat16(v[2 * e + 1]);
        __nv_bfloat16 l0 = __float2bfloat16(v[2 * e]     - __bfloat162float(h0));
        __nv_bfloat16 l1 = __float2bfloat16(v[2 * e + 1] - __bfloat162float(h1));
        __nv_bfloat162 hh = __halves2bfloat162(h0, h1);
        __nv_bfloat162 ll = __halves2bfloat162(l0, l1);
        hp[e] = *(uint32_t*)&hh;
        lp[e] = *(uint32_t*)&ll;
    }
    uint32_t o = bt_off(r, k0);
    *(uint4*)(hi_base + o) = make_uint4(hp[0], hp[1], hp[2], hp[3]);
    *(uint4*)(lo_base + o) = make_uint4(lp[0], lp[1], lp[2], lp[3]);
}
// store a lane's 4 fp32 dims (cols 4*lane..4*lane+3 of row r) as bf16 hi/lo
__device__ __forceinline__ void split_store4(float4 a, char* hi_base, char* lo_base,
                                             int r, int lane) {
    __nv_bfloat16 h0 = __float2bfloat16(a.x), h1 = __float2bfloat16(a.y);
    __nv_bfloat16 h2 = __float2bfloat16(a.z), h3 = __float2bfloat16(a.w);
    __nv_bfloat16 l0 = __float2bfloat16(a.x - __bfloat162float(h0));
    __nv_bfloat16 l1 = __float2bfloat16(a.y - __bfloat162float(h1));
    __nv_bfloat16 l2 = __float2bfloat16(a.z - __bfloat162float(h2));
    __nv_bfloat16 l3 = __float2bfloat16(a.w - __bfloat162float(h3));
    __nv_bfloat162 hA = __halves2bfloat162(h0, h1), hB = __halves2bfloat162(h2, h3);
    __nv_bfloat162 lA = __halves2bfloat162(l0, l1), lB = __halves2bfloat162(l2, l3);
    uint32_t off = bt_off(r, 8 * (lane >> 1)) + (lane & 1) * 8;
    *(uint2*)(hi_base + off) = make_uint2(*(uint32_t*)&hA, *(uint32_t*)&hB);
    *(uint2*)(lo_base + off) = make_uint2(*(uint32_t*)&lA, *(uint32_t*)&lB);
}

// ---------------------------------------------------------------------------
// Shared GEMM mainloop + LN epilogue (device function).
// Assumes XHI/XLO/WHI/WLO + consts populated and __syncthreads() done.
// ---------------------------------------------------------------------------
template<bool ACC>
__device__ __forceinline__ void gemm_ln_epilogue(
    char* smem, uint32_t sb, int tid, int wid, int lane, int gbase,
    float* __restrict__ out)
{
    const int mw = wid & 1;
    const int nw = wid >> 1;
    float* sB = (float*)(smem + OFF_CONST);
    float* sS = sB + 128;
    float* sO = sS + 128;

    float acc[2][4][4];
#pragma unroll
    for (int mt = 0; mt < 2; mt++)
#pragma unroll
        for (int nt = 0; nt < 4; nt++)
#pragma unroll
            for (int e = 0; e < 4; e++) acc[mt][nt][e] = 0.f;

    const uint32_t xhi = sb + OFF_XHI, xlo = sb + OFF_XLO;
    const uint32_t whi = sb + OFF_WHI, wlo = sb + OFF_WLO;

#pragma unroll
    for (int kb8 = 0; kb8 < 8; kb8++) {
        const int kb = kb8 * 16;
        uint32_t ahi[2][4], alo[2][4], bhi[4][2], blo[4][2];
#pragma unroll
        for (int mt = 0; mt < 2; mt++) {
            uint32_t aa = a_addr(xhi, mw * 32 + mt * 16, kb, lane);
            ldsm_x4(ahi[mt][0], ahi[mt][1], ahi[mt][2], ahi[mt][3], aa);
            uint32_t al = a_addr(xlo, mw * 32 + mt * 16, kb, lane);
            ldsm_x4(alo[mt][0], alo[mt][1], alo[mt][2], alo[mt][3], al);
        }
#pragma unroll
        for (int p = 0; p < 2; p++) {
            uint32_t ba = b_addr(whi, nw * 32 + p * 16, kb, lane);
            ldsm_x4(bhi[2*p][0], bhi[2*p][1], bhi[2*p+1][0], bhi[2*p+1][1], ba);
            uint32_t bb = b_addr(wlo, nw * 32 + p * 16, kb, lane);
            ldsm_x4(blo[2*p][0], blo[2*p][1], blo[2*p+1][0], blo[2*p+1][1], bb);
        }
#pragma unroll
        for (int mt = 0; mt < 2; mt++)
#pragma unroll
            for (int nt = 0; nt < 4; nt++) {
                mma_bf16(acc[mt][nt], ahi[mt], bhi[nt][0], bhi[nt][1]);
                mma_bf16(acc[mt][nt], ahi[mt], blo[nt][0], blo[nt][1]);
                mma_bf16(acc[mt][nt], alo[mt], bhi[nt][0], bhi[nt][1]);
            }
    }
    __syncthreads();

    float* stage = (float*)smem;
    {
        const int rsub = lane >> 2;
        const int csub = (lane & 3) * 2;
#pragma unroll
        for (int mt = 0; mt < 2; mt++)
#pragma unroll
            for (int nt = 0; nt < 4; nt++) {
                int row = mw * 32 + mt * 16 + rsub;
                int col = nw * 32 + nt * 8 + csub;
                *(float2*)(stage + row * STAGE_STRIDE + col) =
                    make_float2(acc[mt][nt][0], acc[mt][nt][1]);
                *(float2*)(stage + (row + 8) * STAGE_STRIDE + col) =
                    make_float2(acc[mt][nt][2], acc[mt][nt][3]);
            }
    }
    __syncthreads();

    {
        const int r  = tid >> 2;
        const int qh = tid & 3;
        float* row = stage + r * STAGE_STRIDE + qh * 32;
        float s = 0.f, q = 0.f;
#pragma unroll
        for (int i = 0; i < 8; i++) {
            float4 v = ((float4*)row)[i];
            const int c = qh * 32 + i * 4;
            v.x = fmaxf(v.x + sB[c + 0], 0.f);
            v.y = fmaxf(v.y + sB[c + 1], 0.f);
            v.z = fmaxf(v.z + sB[c + 2], 0.f);
            v.w = fmaxf(v.w + sB[c + 3], 0.f);
            ((float4*)row)[i] = v;
            s += v.x + v.y + v.z + v.w;
            q = fmaf(v.x, v.x, q); q = fmaf(v.y, v.y, q);
            q = fmaf(v.z, v.z, q); q = fmaf(v.w, v.w, q);
        }
        s += __shfl_xor_sync(0xffffffffu, s, 1);
        q += __shfl_xor_sync(0xffffffffu, q, 1);
        s += __shfl_xor_sync(0xffffffffu, s, 2);
        q += __shfl_xor_sync(0xffffffffu, q, 2);
        float mean = s * (1.f / DIM);
        float var  = q * (1.f / DIM) - mean * mean + 1e-9f;
        float rs   = rsqrtf(var);

        const int g = gbase + r;
        if (g < N_NODES) {
            float4* op = (float4*)(out + (size_t)g * DIM + qh * 32);
#pragma unroll
            for (int i = 0; i < 8; i++) {
                float4 v = ((float4*)row)[i];
                const int c = qh * 32 + i * 4;
                float4 rv;
                rv.x = (v.x - mean) * rs * sS[c + 0] + sO[c + 0];
                rv.y = (v.y - mean) * rs * sS[c + 1] + sO[c + 1];
                rv.z = (v.z - mean) * rs * sS[c + 2] + sO[c + 2];
                rv.w = (v.w - mean) * rs * sS[c + 3] + sO[c + 3];
                if (ACC) {
                    float4 p = op[i];
                    rv.x += p.x; rv.y += p.y; rv.z += p.z; rv.w += p.w;
                }
                op[i] = rv;
            }
        }
    }
}

__device__ __forceinline__ void load_w_consts(
    char* smem, int tid, const float* __restrict__ W,
    const float* __restrict__ bias, const float* __restrict__ scale,
    const float* __restrict__ offset, int so)
{
    for (int i = tid; i < 2048; i += 256) {
        int r = i >> 4, k0 = (i & 15) << 3;
        split_store8(W + r * DIM + k0, smem + OFF_WHI, smem + OFF_WLO, r, k0);
    }
    float* sB = (float*)(smem + OFF_CONST);
    float* sS = sB + 128;
    float* sO = sS + 128;
    if (tid < 32)       ((float4*)sB)[tid]      = ((const float4*)bias)[tid];
    else if (tid < 64)  ((float4*)sS)[tid - 32] = ((const float4*)(scale  + so))[tid - 32];
    else if (tid < 96)  ((float4*)sO)[tid - 64] = ((const float4*)(offset + so))[tid - 64];
}

// ---------------------------------------------------------------------------
// Self branch: X loaded from feat_in.
// ---------------------------------------------------------------------------
__global__ void __launch_bounds__(256, 2) mma_branch_self(
    const float* __restrict__ X, const float* __restrict__ W,
    const float* __restrict__ bias, const float* __restrict__ scale,
    const float* __restrict__ offset, float* __restrict__ out)
{
    extern __shared__ char smem[];
    const uint32_t sb = smem_u32(smem);
    const int tid = threadIdx.x, wid = tid >> 5, lane = tid & 31;
    const int gbase = blockIdx.x * TILE_M;

    load_w_consts(smem, tid, W, bias, scale, offset, 0);
    for (int i = tid; i < 1024; i += 256) {
        int r = i >> 4, k0 = (i & 15) << 3;
        int gr = gbase + r; if (gr >= N_NODES) gr = N_NODES - 1;
        split_store8(X + (size_t)gr * DIM + k0, smem + OFF_XHI, smem + OFF_XLO, r, k0);
    }
    __syncthreads();
    gemm_ln_epilogue<false>(smem, sb, tid, wid, lane, gbase, out);
}

// ---------------------------------------------------------------------------
// Fused neigh branch: each warp gathers 8 nodes' neighbor sums (warp-per-node,
// lane = float4 of 4 dims) straight into the swizzled bf16 hi/lo X tile.
// No g_neigh round trip.
// ---------------------------------------------------------------------------
__global__ void __launch_bounds__(256, 2) mma_branch_gather(
    const float4* __restrict__ feat4, const int* __restrict__ ofs,
    const int* __restrict__ scol, const float* __restrict__ sval,
    const float* __restrict__ W, const float* __restrict__ bias,
    const float* __restrict__ scale, const float* __restrict__ offset,
    float* __restrict__ out)
{
    extern __shared__ char smem[];
    const uint32_t sb = smem_u32(smem);
    const int tid = threadIdx.x, wid = tid >> 5, lane = tid & 31;
    const int gbase = blockIdx.x * TILE_M;

    load_w_consts(smem, tid, W, bias, scale, offset, DIM);

    // gather 8 nodes per warp into the X tile
    for (int rr = 0; rr < 8; rr++) {
        const int r = wid * 8 + rr;
        const int node = gbase + r;
        float4 acc = make_float4(0.f, 0.f, 0.f, 0.f);
        if (node < N_NODES) {
            const int beg = ofs[node];
            const int end = ofs[node + 1];
            int e = beg;
            for (; e + 4 <= end; e += 4) {
                int   c0 = scol[e + 0], c1 = scol[e + 1], c2 = scol[e + 2], c3 = scol[e + 3];
                float v0 = sval[e + 0], v1 = sval[e + 1], v2 = sval[e + 2], v3 = sval[e + 3];
                float4 x0 = feat4[(size_t)c0 * 32 + lane];
                float4 x1 = feat4[(size_t)c1 * 32 + lane];
                float4 x2 = feat4[(size_t)c2 * 32 + lane];
                float4 x3 = feat4[(size_t)c3 * 32 + lane];
                acc.x = fmaf(v0, x0.x, acc.x); acc.y = fmaf(v0, x0.y, acc.y);
                acc.z = fmaf(v0, x0.z, acc.z); acc.w = fmaf(v0, x0.w, acc.w);
                acc.x = fmaf(v1, x1.x, acc.x); acc.y = fmaf(v1, x1.y, acc.y);
                acc.z = fmaf(v1, x1.z, acc.z); acc.w = fmaf(v1, x1.w, acc.w);
                acc.x = fmaf(v2, x2.x, acc.x); acc.y = fmaf(v2, x2.y, acc.y);
                acc.z = fmaf(v2, x2.z, acc.z); acc.w = fmaf(v2, x2.w, acc.w);
                acc.x = fmaf(v3, x3.x, acc.x); acc.y = fmaf(v3, x3.y, acc.y);
                acc.z = fmaf(v3, x3.z, acc.z); acc.w = fmaf(v3, x3.w, acc.w);
            }
            for (; e < end; e++) {
                int   c = scol[e];
                float v = sval[e];
                float4 x = feat4[(size_t)c * 32 + lane];
                acc.x = fmaf(v, x.x, acc.x); acc.y = fmaf(v, x.y, acc.y);
                acc.z = fmaf(v, x.z, acc.z); acc.w = fmaf(v, x.w, acc.w);
            }
        }
        split_store4(acc, smem + OFF_XHI, smem + OFF_XLO, r, lane);
    }
    __syncthreads();
    gemm_ln_epilogue<true>(smem, sb, tid, wid, lane, gbase, out);
}

// ---------------------------------------------------------------------------
struct ForkResources {
    cudaStream_t s2  = nullptr;
    cudaEvent_t  ev1 = nullptr, ev2 = nullptr;
    bool ok = false;
    ForkResources() {
        if (cudaStreamCreateWithFlags(&s2, cudaStreamNonBlocking) != cudaSuccess) return;
        if (cudaEventCreateWithFlags(&ev1, cudaEventDisableTiming) != cudaSuccess) return;
        if (cudaEventCreateWithFlags(&ev2, cudaEventDisableTiming) != cudaSuccess) return;
        ok = true;
    }
};
static ForkResources g_fork;

// ---------------------------------------------------------------------------
// stream0: zero_cnt -> count -> bsum -> scan_bsums -> offsets -> fill --\
// s2:      mma_self -----------------------------------------------------join-> mma_gather
// ---------------------------------------------------------------------------
extern "C" void kernel_launch(void* const* d_in, const int* in_sizes, int n_in,
                              void* d_out, int out_size) {
    const float* feat_in  = (const float*)d_in[0];
    const int*   edge_row = (const int*)  d_in[1];
    const int*   edge_col = (const int*)  d_in[2];
    const float* edge_val = (const float*)d_in[3];
    const float* W_self   = (const float*)d_in[4];
    const float* b_self   = (const float*)d_in[5];
    const float* W_neigh  = (const float*)d_in[6];
    const float* b_neigh  = (const float*)d_in[7];
    const float* scale    = (const float*)d_in[8];
    const float* offset   = (const float*)d_in[9];
    float* out = (float*)d_out;

    float *sval;
    int *cnt, *ofs, *cur, *scol, *bsum, *bbase;
    cudaGetSymbolAddress((void**)&cnt,   g_cnt);
    cudaGetSymbolAddress((void**)&ofs,   g_ofs);
    cudaGetSymbolAddress((void**)&cur,   g_cur);
    cudaGetSymbolAddress((void**)&scol,  g_scol);
    cudaGetSymbolAddress((void**)&sval,  g_sval);
    cudaGetSymbolAddress((void**)&bsum,  g_bsum);
    cudaGetSymbolAddress((void**)&bbase, g_bbase);

    cudaFuncSetAttribute(mma_branch_self,
                         cudaFuncAttributeMaxDynamicSharedMemorySize, GEMM_SMEM);
    cudaFuncSetAttribute(mma_branch_gather,
                         cudaFuncAttributeMaxDynamicSharedMemorySize, GEMM_SMEM);

    const int eb = (N_EDGES + 255) / 256;
    const int nb = (N_NODES + 255) / 256;

    if (g_fork.ok) {
        cudaEventRecord(g_fork.ev1, 0);
        cudaStreamWaitEvent(g_fork.s2, g_fork.ev1, 0);

        mma_branch_self<<<N_TILES, 256, GEMM_SMEM, g_fork.s2>>>(
            feat_in, W_self, b_self, scale, offset, out);

        zero_cnt_kernel<<<nb, 256>>>(cnt);
        count_kernel<<<eb, 256>>>(edge_row, cnt);
        bsum_kernel<<<NB_SCAN, SCAN_BS>>>(cnt, bsum);
        scan_bsums<<<1, 256>>>(bsum, bbase);
        offsets_kernel<<<NB_SCAN, SCAN_BS>>>(cnt, bbase, ofs, cur);
        fill_kernel<<<eb, 256>>>(edge_row, edge_col, edge_val, cur, scol, sval);

        cudaEventRecord(g_fork.ev2, g_fork.s2);
        cudaStreamWaitEvent(0, g_fork.ev2, 0);

        mma_branch_gather<<<N_TILES, 256, GEMM_SMEM>>>(
            (const float4*)feat_in, ofs, scol, sval,
            W_neigh, b_neigh, scale, offset, out);
    } else {
        zero_cnt_kernel<<<nb, 256>>>(cnt);
        count_kernel<<<eb, 256>>>(edge_row, cnt);
        bsum_kernel<<<NB_SCAN, SCAN_BS>>>(cnt, bsum);
        scan_bsums<<<1, 256>>>(bsum, bbase);
        offsets_kernel<<<NB_SCAN, SCAN_BS>>>(cnt, bbase, ofs, cur);
        fill_kernel<<<eb, 256>>>(edge_row, edge_col, edge_val, cur, scol, sval);
        mma_branch_self<<<N_TILES, 256, GEMM_SMEM>>>(
            feat_in, W_self, b_self, scale, offset, out);
        mma_branch_gather<<<N_TILES, 256, GEMM_SMEM>>>(
            (const float4*)feat_in, ofs, scol, sval,
            W_neigh, b_neigh, scale, offset, out);
    }
}

// round 12
// speedup vs baseline: 1.0990x; 1.0990x over previous
#include <cuda_runtime.h>
#include <cuda_bf16.h>
#include <cstdint>

#define N_NODES 50000
#define N_EDGES 800000
#define DIM     128

#define TILE_M   64
#define N_TILES  ((N_NODES + TILE_M - 1) / TILE_M)   // 782

// ---------------- SMEM layout (bytes, dynamic) ----------------------------
#define OFF_XHI   0
#define OFF_XLO   16384
#define OFF_WHI   32768
#define OFF_WLO   65536
#define OFF_CONST 98304                  // bias/scale/offset: 3 x 512B
#define GEMM_SMEM (98304 + 1536)
#define STAGE_STRIDE 132                 // fp32 stage [64][132] overlays X tiles

// ---------------- scan partition ------------------------------------------
#define SCAN_BS   256
#define NB_SCAN   ((N_NODES + SCAN_BS - 1) / SCAN_BS)   // 196

// ---------------- scratch (__device__ globals; no allocs allowed) ---------
__device__ float g_neigh[(size_t)N_NODES * DIM];
__device__ int   g_cnt[N_NODES];
__device__ int   g_ofs[N_NODES + 1];
__device__ int   g_cur[N_NODES];
__device__ int2  g_pack[N_EDGES];        // (col, __float_as_int(val))
__device__ int   g_bsum[NB_SCAN];
__device__ int   g_bbase[NB_SCAN];

// ---------------------------------------------------------------------------
__global__ void zero_cnt_kernel(int* __restrict__ cnt) {
    int i = blockIdx.x * blockDim.x + threadIdx.x;
    if (i < N_NODES) cnt[i] = 0;
}

__global__ void count_kernel(const int* __restrict__ erow, int* __restrict__ cnt) {
    int e = blockIdx.x * blockDim.x + threadIdx.x;
    if (e < N_EDGES) atomicAdd(&cnt[erow[e]], 1);
}

__global__ void __launch_bounds__(SCAN_BS) bsum_kernel(const int* __restrict__ cnt,
                                                       int* __restrict__ bsum) {
    __shared__ int red[SCAN_BS / 32];
    int i = blockIdx.x * SCAN_BS + threadIdx.x;
    int v = (i < N_NODES) ? cnt[i] : 0;
#pragma unroll
    for (int o = 16; o; o >>= 1) v += __shfl_xor_sync(0xffffffffu, v, o);
    if ((threadIdx.x & 31) == 0) red[threadIdx.x >> 5] = v;
    __syncthreads();
    if (threadIdx.x == 0) {
        int s = 0;
#pragma unroll
        for (int w = 0; w < SCAN_BS / 32; w++) s += red[w];
        bsum[blockIdx.x] = s;
    }
}

__global__ void __launch_bounds__(256) scan_bsums(const int* __restrict__ bsum,
                                                  int* __restrict__ bbase) {
    __shared__ int sh[256];
    int t = threadIdx.x;
    sh[t] = (t < NB_SCAN) ? bsum[t] : 0;
    __syncthreads();
#pragma unroll
    for (int o = 1; o < 256; o <<= 1) {
        int v = (t >= o) ? sh[t - o] : 0;
        __syncthreads();
        sh[t] += v;
        __syncthreads();
    }
    if (t < NB_SCAN) bbase[t] = (t == 0) ? 0 : sh[t - 1];
}

__global__ void __launch_bounds__(SCAN_BS) offsets_kernel(
    const int* __restrict__ cnt, const int* __restrict__ bbase,
    int* __restrict__ ofs, int* __restrict__ cur)
{
    __shared__ int sh[SCAN_BS];
    int t = threadIdx.x;
    int i = blockIdx.x * SCAN_BS + t;
    int v = (i < N_NODES) ? cnt[i] : 0;
    sh[t] = v;
    __syncthreads();
#pragma unroll
    for (int o = 1; o < SCAN_BS; o <<= 1) {
        int u = (t >= o) ? sh[t - o] : 0;
        __syncthreads();
        sh[t] += u;
        __syncthreads();
    }
    if (i < N_NODES) {
        int excl = bbase[blockIdx.x] + sh[t] - v;
        ofs[i] = excl;
        cur[i] = excl;
    }
    if (i == N_NODES - 1) ofs[N_NODES] = N_EDGES;
}

__global__ void fill_kernel(const int* __restrict__ erow, const int* __restrict__ ecol,
                            const float* __restrict__ eval_,
                            int* __restrict__ cur, int2* __restrict__ pack) {
    int e = blockIdx.x * blockDim.x + threadIdx.x;
    if (e >= N_EDGES) return;
    int p = atomicAdd(&cur[erow[e]], 1);
    pack[p] = make_int2(ecol[e], __float_as_int(eval_[e]));
}

// ---------------------------------------------------------------------------
// gather aggregation: WARP per node, lane = float4 of 4 dims.
// Packed (col,val) int2 broadcast loads; edge loop unrolled x8 -> 8 independent
// 512B gathers in flight; no smem, no barriers.
// ---------------------------------------------------------------------------
__global__ void __launch_bounds__(256, 4) gather_kernel(
    const float4* __restrict__ feat4, const int* __restrict__ ofs,
    const int2* __restrict__ pack, float4* __restrict__ neigh4)
{
    const int node = (blockIdx.x * blockDim.x + threadIdx.x) >> 5;
    const int lane = threadIdx.x & 31;
    if (node >= N_NODES) return;
    const int beg = ofs[node];
    const int end = ofs[node + 1];

    float4 acc = make_float4(0.f, 0.f, 0.f, 0.f);
    int e = beg;
    for (; e + 8 <= end; e += 8) {
        int2 p[8];
        float4 x[8];
#pragma unroll
        for (int i = 0; i < 8; i++) p[i] = pack[e + i];
#pragma unroll
        for (int i = 0; i < 8; i++) x[i] = feat4[(size_t)p[i].x * 32 + lane];
#pragma unroll
        for (int i = 0; i < 8; i++) {
            float v = __int_as_float(p[i].y);
            acc.x = fmaf(v, x[i].x, acc.x); acc.y = fmaf(v, x[i].y, acc.y);
            acc.z = fmaf(v, x[i].z, acc.z); acc.w = fmaf(v, x[i].w, acc.w);
        }
    }
    for (; e + 4 <= end; e += 4) {
        int2 p[4];
        float4 x[4];
#pragma unroll
        for (int i = 0; i < 4; i++) p[i] = pack[e + i];
#pragma unroll
        for (int i = 0; i < 4; i++) x[i] = feat4[(size_t)p[i].x * 32 + lane];
#pragma unroll
        for (int i = 0; i < 4; i++) {
            float v = __int_as_float(p[i].y);
            acc.x = fmaf(v, x[i].x, acc.x); acc.y = fmaf(v, x[i].y, acc.y);
            acc.z = fmaf(v, x[i].z, acc.z); acc.w = fmaf(v, x[i].w, acc.w);
        }
    }
    for (; e < end; e++) {
        int2 p = pack[e];
        float v = __int_as_float(p.y);
        float4 x = feat4[(size_t)p.x * 32 + lane];
        acc.x = fmaf(v, x.x, acc.x); acc.y = fmaf(v, x.y, acc.y);
        acc.z = fmaf(v, x.z, acc.z); acc.w = fmaf(v, x.w, acc.w);
    }
    neigh4[(size_t)node * 32 + lane] = acc;
}

// ---------------------------------------------------------------------------
__device__ __forceinline__ uint32_t smem_u32(const void* p) {
    uint32_t a;
    asm("{ .reg .u64 t; cvta.to.shared.u64 t, %1; cvt.u32.u64 %0, t; }" : "=r"(a) : "l"(p));
    return a;
}
__device__ __forceinline__ void ldsm_x4(uint32_t& r0, uint32_t& r1,
                                        uint32_t& r2, uint32_t& r3, uint32_t a) {
    asm volatile("ldmatrix.sync.aligned.m8n8.x4.shared.b16 {%0,%1,%2,%3}, [%4];"
                 : "=r"(r0), "=r"(r1), "=r"(r2), "=r"(r3) : "r"(a));
}
__device__ __forceinline__ void mma_bf16(float* c, const uint32_t* a,
                                         uint32_t b0, uint32_t b1) {
    asm volatile("mma.sync.aligned.m16n8k16.row.col.f32.bf16.bf16.f32 "
                 "{%0,%1,%2,%3}, {%4,%5,%6,%7}, {%8,%9}, {%0,%1,%2,%3};"
                 : "+f"(c[0]), "+f"(c[1]), "+f"(c[2]), "+f"(c[3])
                 : "r"(a[0]), "r"(a[1]), "r"(a[2]), "r"(a[3]), "r"(b0), "r"(b1));
}
__device__ __forceinline__ uint32_t bt_off(int r, int k0) {
    return (uint32_t)(r * 256 + ((((k0 >> 3) ^ (r & 7)) & 15) << 4));
}
__device__ __forceinline__ uint32_t a_addr(uint32_t base, int m0, int kb, int lane) {
    int row = m0 + (lane & 15);
    int chunk = (kb >> 3) + (lane >> 4);
    return base + row * 256 + (((chunk ^ (row & 7)) & 15) << 4);
}
__device__ __forceinline__ uint32_t b_addr(uint32_t base, int n0, int kb, int lane) {
    int row = n0 + (lane & 7) + ((lane >> 4) << 3);
    int chunk = (kb >> 3) + ((lane >> 3) & 1);
    return base + row * 256 + (((chunk ^ (row & 7)) & 15) << 4);
}
__device__ __forceinline__ void split_store8(const float* src, char* hi_base, char* lo_base,
                                             int r, int k0) {
    float4 a = ((const float4*)src)[0];
    float4 b = ((const float4*)src)[1];
    float v[8] = {a.x, a.y, a.z, a.w, b.x, b.y, b.z, b.w};
    uint32_t hp[4], lp[4];
#pragma unroll
    for (int e = 0; e < 4; e++) {
        __nv_bfloat16 h0 = __float2bfloat16(v[2 * e]);
        __nv_bfloat16 h1 = __float2bfloat16(v[2 * e + 1]);
        __nv_bfloat16 l0 = __float2bfloat16(v[2 * e]     - __bfloat162float(h0));
        __nv_bfloat16 l1 = __float2bfloat16(v[2 * e + 1] - __bfloat162float(h1));
        __nv_bfloat162 hh = __halves2bfloat162(h0, h1);
        __nv_bfloat162 ll = __halves2bfloat162(l0, l1);
        hp[e] = *(uint32_t*)&hh;
        lp[e] = *(uint32_t*)&ll;
    }
    uint32_t o = bt_off(r, k0);
    *(uint4*)(hi_base + o) = make_uint4(hp[0], hp[1], hp[2], hp[3]);
    *(uint4*)(lo_base + o) = make_uint4(lp[0], lp[1], lp[2], lp[3]);
}

// ---------------------------------------------------------------------------
// Tensor branch (mma.sync bf16 3-term split), TILE_M=64, 2 CTAs/SM:
//   out (+)= LN(relu(X @ W^T + b)) * scale + offset
// ---------------------------------------------------------------------------
template<bool ACC>
__global__ void __launch_bounds__(256, 2) mma_branch(
    const float* __restrict__ X, const float* __restrict__ W,
    const float* __restrict__ bias, const float* __restrict__ scale,
    const float* __restrict__ offset, int so, float* __restrict__ out)
{
    extern __shared__ char smem[];
    const uint32_t sb = smem_u32(smem);
    const int tid  = threadIdx.x;
    const int wid  = tid >> 5;
    const int lane = tid & 31;
    const int mw   = wid & 1;
    const int nw   = wid >> 1;
    const int gbase = blockIdx.x * TILE_M;

    for (int i = tid; i < 2048; i += 256) {
        int r = i >> 4, k0 = (i & 15) << 3;
        split_store8(W + r * DIM + k0, smem + OFF_WHI, smem + OFF_WLO, r, k0);
    }
    for (int i = tid; i < 1024; i += 256) {
        int r = i >> 4, k0 = (i & 15) << 3;
        int gr = gbase + r; if (gr >= N_NODES) gr = N_NODES - 1;
        split_store8(X + (size_t)gr * DIM + k0, smem + OFF_XHI, smem + OFF_XLO, r, k0);
    }
    float* sB = (float*)(smem + OFF_CONST);
    float* sS = sB + 128;
    float* sO = sS + 128;
    if (tid < 32)       ((float4*)sB)[tid]      = ((const float4*)bias)[tid];
    else if (tid < 64)  ((float4*)sS)[tid - 32] = ((const float4*)(scale  + so))[tid - 32];
    else if (tid < 96)  ((float4*)sO)[tid - 64] = ((const float4*)(offset + so))[tid - 64];
    __syncthreads();

    float acc[2][4][4];
#pragma unroll
    for (int mt = 0; mt < 2; mt++)
#pragma unroll
        for (int nt = 0; nt < 4; nt++)
#pragma unroll
            for (int e = 0; e < 4; e++) acc[mt][nt][e] = 0.f;

    const uint32_t xhi = sb + OFF_XHI, xlo = sb + OFF_XLO;
    const uint32_t whi = sb + OFF_WHI, wlo = sb + OFF_WLO;

#pragma unroll
    for (int kb8 = 0; kb8 < 8; kb8++) {
        const int kb = kb8 * 16;
        uint32_t ahi[2][4], alo[2][4], bhi[4][2], blo[4][2];
#pragma unroll
        for (int mt = 0; mt < 2; mt++) {
            uint32_t aa = a_addr(xhi, mw * 32 + mt * 16, kb, lane);
            ldsm_x4(ahi[mt][0], ahi[mt][1], ahi[mt][2], ahi[mt][3], aa);
            uint32_t al = a_addr(xlo, mw * 32 + mt * 16, kb, lane);
            ldsm_x4(alo[mt][0], alo[mt][1], alo[mt][2], alo[mt][3], al);
        }
#pragma unroll
        for (int p = 0; p < 2; p++) {
            uint32_t ba = b_addr(whi, nw * 32 + p * 16, kb, lane);
            ldsm_x4(bhi[2*p][0], bhi[2*p][1], bhi[2*p+1][0], bhi[2*p+1][1], ba);
            uint32_t bb = b_addr(wlo, nw * 32 + p * 16, kb, lane);
            ldsm_x4(blo[2*p][0], blo[2*p][1], blo[2*p+1][0], blo[2*p+1][1], bb);
        }
#pragma unroll
        for (int mt = 0; mt < 2; mt++)
#pragma unroll
            for (int nt = 0; nt < 4; nt++) {
                mma_bf16(acc[mt][nt], ahi[mt], bhi[nt][0], bhi[nt][1]);
                mma_bf16(acc[mt][nt], ahi[mt], blo[nt][0], blo[nt][1]);
                mma_bf16(acc[mt][nt], alo[mt], bhi[nt][0], bhi[nt][1]);
            }
    }
    __syncthreads();

    float* stage = (float*)smem;
    {
        const int rsub = lane >> 2;
        const int csub = (lane & 3) * 2;
#pragma unroll
        for (int mt = 0; mt < 2; mt++)
#pragma unroll
            for (int nt = 0; nt < 4; nt++) {
                int row = mw * 32 + mt * 16 + rsub;
                int col = nw * 32 + nt * 8 + csub;
                *(float2*)(stage + row * STAGE_STRIDE + col) =
                    make_float2(acc[mt][nt][0], acc[mt][nt][1]);
                *(float2*)(stage + (row + 8) * STAGE_STRIDE + col) =
                    make_float2(acc[mt][nt][2], acc[mt][nt][3]);
            }
    }
    __syncthreads();

    {
        const int r  = tid >> 2;
        const int qh = tid & 3;
        float* row = stage + r * STAGE_STRIDE + qh * 32;
        float s = 0.f, q = 0.f;
#pragma unroll
        for (int i = 0; i < 8; i++) {
            float4 v = ((float4*)row)[i];
            const int c = qh * 32 + i * 4;
            v.x = fmaxf(v.x + sB[c + 0], 0.f);
            v.y = fmaxf(v.y + sB[c + 1], 0.f);
            v.z = fmaxf(v.z + sB[c + 2], 0.f);
            v.w = fmaxf(v.w + sB[c + 3], 0.f);
            ((float4*)row)[i] = v;
            s += v.x + v.y + v.z + v.w;
            q = fmaf(v.x, v.x, q); q = fmaf(v.y, v.y, q);
            q = fmaf(v.z, v.z, q); q = fmaf(v.w, v.w, q);
        }
        s += __shfl_xor_sync(0xffffffffu, s, 1);
        q += __shfl_xor_sync(0xffffffffu, q, 1);
        s += __shfl_xor_sync(0xffffffffu, s, 2);
        q += __shfl_xor_sync(0xffffffffu, q, 2);
        float mean = s * (1.f / DIM);
        float var  = q * (1.f / DIM) - mean * mean + 1e-9f;
        float rs   = rsqrtf(var);

        const int g = gbase + r;
        if (g < N_NODES) {
            float4* op = (float4*)(out + (size_t)g * DIM + qh * 32);
#pragma unroll
            for (int i = 0; i < 8; i++) {
                float4 v = ((float4*)row)[i];
                const int c = qh * 32 + i * 4;
                float4 rv;
                rv.x = (v.x - mean) * rs * sS[c + 0] + sO[c + 0];
                rv.y = (v.y - mean) * rs * sS[c + 1] + sO[c + 1];
                rv.z = (v.z - mean) * rs * sS[c + 2] + sO[c + 2];
                rv.w = (v.w - mean) * rs * sS[c + 3] + sO[c + 3];
                if (ACC) {
                    float4 p = op[i];
                    rv.x += p.x; rv.y += p.y; rv.z += p.z; rv.w += p.w;
                }
                op[i] = rv;
            }
        }
    }
}

// ---------------------------------------------------------------------------
struct ForkResources {
    cudaStream_t s2  = nullptr;
    cudaEvent_t  ev1 = nullptr, ev2 = nullptr;
    bool ok = false;
    ForkResources() {
        if (cudaStreamCreateWithFlags(&s2, cudaStreamNonBlocking) != cudaSuccess) return;
        if (cudaEventCreateWithFlags(&ev1, cudaEventDisableTiming) != cudaSuccess) return;
        if (cudaEventCreateWithFlags(&ev2, cudaEventDisableTiming) != cudaSuccess) return;
        ok = true;
    }
};
static ForkResources g_fork;

// ---------------------------------------------------------------------------
// stream0: zero_cnt -> count -> bsum -> scan_bsums -> offsets -> fill -> gather
// s2:      mma_self  ----------------------------------------------- join -> mma_neigh(ACC)
// ---------------------------------------------------------------------------
extern "C" void kernel_launch(void* const* d_in, const int* in_sizes, int n_in,
                              void* d_out, int out_size) {
    const float* feat_in  = (const float*)d_in[0];
    const int*   edge_row = (const int*)  d_in[1];
    const int*   edge_col = (const int*)  d_in[2];
    const float* edge_val = (const float*)d_in[3];
    const float* W_self   = (const float*)d_in[4];
    const float* b_self   = (const float*)d_in[5];
    const float* W_neigh  = (const float*)d_in[6];
    const float* b_neigh  = (const float*)d_in[7];
    const float* scale    = (const float*)d_in[8];
    const float* offset   = (const float*)d_in[9];
    float* out = (float*)d_out;

    float *neigh;
    int *cnt, *ofs, *cur, *bsum, *bbase;
    int2 *pack;
    cudaGetSymbolAddress((void**)&neigh, g_neigh);
    cudaGetSymbolAddress((void**)&cnt,   g_cnt);
    cudaGetSymbolAddress((void**)&ofs,   g_ofs);
    cudaGetSymbolAddress((void**)&cur,   g_cur);
    cudaGetSymbolAddress((void**)&pack,  g_pack);
    cudaGetSymbolAddress((void**)&bsum,  g_bsum);
    cudaGetSymbolAddress((void**)&bbase, g_bbase);

    cudaFuncSetAttribute(mma_branch<false>,
                         cudaFuncAttributeMaxDynamicSharedMemorySize, GEMM_SMEM);
    cudaFuncSetAttribute(mma_branch<true>,
                         cudaFuncAttributeMaxDynamicSharedMemorySize, GEMM_SMEM);

    const int eb = (N_EDGES + 255) / 256;
    const int nb = (N_NODES + 255) / 256;
    const int gb = (N_NODES * 32 + 255) / 256;   // gather: warp per node

    if (g_fork.ok) {
        cudaEventRecord(g_fork.ev1, 0);
        cudaStreamWaitEvent(g_fork.s2, g_fork.ev1, 0);

        mma_branch<false><<<N_TILES, 256, GEMM_SMEM, g_fork.s2>>>(
            feat_in, W_self, b_self, scale, offset, 0, out);

        zero_cnt_kernel<<<nb, 256>>>(cnt);
        count_kernel<<<eb, 256>>>(edge_row, cnt);
        bsum_kernel<<<NB_SCAN, SCAN_BS>>>(cnt, bsum);
        scan_bsums<<<1, 256>>>(bsum, bbase);
        offsets_kernel<<<NB_SCAN, SCAN_BS>>>(cnt, bbase, ofs, cur);
        fill_kernel<<<eb, 256>>>(edge_row, edge_col, edge_val, cur, pack);
        gather_kernel<<<gb, 256>>>((const float4*)feat_in, ofs, pack, (float4*)neigh);

        cudaEventRecord(g_fork.ev2, g_fork.s2);
        cudaStreamWaitEvent(0, g_fork.ev2, 0);

        mma_branch<true><<<N_TILES, 256, GEMM_SMEM>>>(
            neigh, W_neigh, b_neigh, scale, offset, DIM, out);
    } else {
        zero_cnt_kernel<<<nb, 256>>>(cnt);
        count_kernel<<<eb, 256>>>(edge_row, cnt);
        bsum_kernel<<<NB_SCAN, SCAN_BS>>>(cnt, bsum);
        scan_bsums<<<1, 256>>>(bsum, bbase);
        offsets_kernel<<<NB_SCAN, SCAN_BS>>>(cnt, bbase, ofs, cur);
        fill_kernel<<<eb, 256>>>(edge_row, edge_col, edge_val, cur, pack);
        mma_branch<false><<<N_TILES, 256, GEMM_SMEM>>>(
            feat_in, W_self, b_self, scale, offset, 0, out);
        gather_kernel<<<gb, 256>>>((const float4*)feat_in, ofs, pack, (float4*)neigh);
        mma_branch<true><<<N_TILES, 256, GEMM_SMEM>>>(
            neigh, W_neigh, b_neigh, scale, offset, DIM, out);
    }
}